// round 2
// baseline (speedup 1.0000x reference)
#include <cuda_runtime.h>
#include <cstdint>

// Problem constants (match reference_code)
#define N_PRE    50000
#define VEC_DIM  300        // 75 float4
#define HIDDEN   128        // 32 float4
#define IN_SIZE  50000      // VOCAB - N_PRE
#define OUT_DIM  428        // VEC_DIM + HIDDEN = 107 float4
#define N_TOKENS (64 * 200)

// One block (128 threads) per token.
// Row layout: out[t*428 + 0:300] = vector part, out[t*428 + 300:428] = hidden part.
// 428 floats = 1712 bytes = 107 float4 -> every row start is 16B aligned.
// vectors row = 300 floats = 1200 bytes = 75 float4 -> 16B aligned.
__global__ __launch_bounds__(128) void encoder_kernel(
    const int*    __restrict__ tokens,    // [N_TOKENS]
    const float4* __restrict__ vectors4,  // [N_PRE * 75]
    const float*  __restrict__ W,         // [HIDDEN, IN_SIZE] row-major
    const float*  __restrict__ b,         // [HIDDEN]
    float4*       __restrict__ out4)      // [N_TOKENS * 107]
{
    const int t   = blockIdx.x;
    const int tid = threadIdx.x;
    const int tok = tokens[t];            // broadcast load, one sector

    float4* orow = out4 + (size_t)t * (OUT_DIM / 4);

    if (tok < N_PRE) {
        // vector part: copy 75 float4 from the pretrained row
        const float4* vrow = vectors4 + (size_t)tok * (VEC_DIM / 4);
        if (tid < 75) orow[tid] = vrow[tid];        // 75 <= 128: single shot
        // hidden part: bias only (32 float4)
        if (tid < 32) {
            const float4* b4 = reinterpret_cast<const float4*>(b);
            orow[75 + tid] = b4[tid];
        }
    } else {
        // vector part: zeros
        const float4 z = make_float4(0.f, 0.f, 0.f, 0.f);
        if (tid < 75) orow[tid] = z;
        // hidden part: b[h] + W[h, tok - N_PRE]  (strided column gather,
        // 128 independent loads per block -> high MLP hides DRAM latency)
        const int c = tok - N_PRE;        // 0 <= c < IN_SIZE guaranteed
        float v = b[tid] + __ldg(&W[(size_t)tid * IN_SIZE + c]);
        float* orow_s = reinterpret_cast<float*>(orow);
        orow_s[VEC_DIM + tid] = v;
    }
}

extern "C" void kernel_launch(void* const* d_in, const int* in_sizes, int n_in,
                              void* d_out, int out_size)
{
    // metadata order: tokens (int32), vectors (f32), W (f32), b (f32)
    const int*    tokens  = (const int*)   d_in[0];
    const float4* vectors = (const float4*)d_in[1];
    const float*  W       = (const float*) d_in[2];
    const float*  b       = (const float*) d_in[3];
    float4*       out     = (float4*)      d_out;

    encoder_kernel<<<N_TOKENS, 128>>>(tokens, vectors, W, b, out);
}